// round 14
// baseline (speedup 1.0000x reference)
#include <cuda_runtime.h>
#include <math.h>
#include <float.h>

#define NB      64
#define TOKENS  784
#define DIM     768
#define FH      28
#define IMG     448
#define TOPK    8
#define PATCH   16

__device__ float g_dist[NB * TOKENS];
__device__ int   g_box[NB][4];   // x0, x1, y0, y1

// ---------------------------------------------------------------------------
// Kernel 1: score = dot(g, l) / ||l||  (g-norm positive per-batch constant
// -> same ordering as cosine). grid (64,49) x 256, 2 rows per warp (the
// empirically best config: 3136 blocks, 12 in-flight LDG.128 per warp).
// ---------------------------------------------------------------------------
__global__ void __launch_bounds__(256) sim_kernel(const float* __restrict__ x) {
    int b = blockIdx.x;
    int s = blockIdx.y;                       // 0..48 -> 16 rows per block
    const float* xb = x + (size_t)b * 785 * DIM;

    __shared__ float4 g_sh[DIM / 4];          // CLS token, 3 KB
    int tid = threadIdx.x;
    if (tid < DIM / 4) g_sh[tid] = ((const float4*)xb)[tid];
    __syncthreads();

    int warp = tid >> 5, lane = tid & 31;
    int r = s * 16 + warp * 2;                // this warp's row pair
    const float4* l0 = (const float4*)(xb + (size_t)(1 + r) * DIM);
    const float4* l1 = (const float4*)(xb + (size_t)(2 + r) * DIM);
    float d0 = 0.f, n0 = 0.f, d1 = 0.f, n1 = 0.f;
#pragma unroll
    for (int j = 0; j < 6; ++j) {
        float4 a = l0[lane + 32 * j];
        float4 c = l1[lane + 32 * j];
        float4 g = g_sh[lane + 32 * j];
        d0 += a.x * g.x + a.y * g.y + a.z * g.z + a.w * g.w;
        n0 += a.x * a.x + a.y * a.y + a.z * a.z + a.w * a.w;
        d1 += c.x * g.x + c.y * g.y + c.z * g.z + c.w * g.w;
        n1 += c.x * c.x + c.y * c.y + c.z * c.z + c.w * c.w;
    }
#pragma unroll
    for (int off = 16; off; off >>= 1) {
        d0 += __shfl_xor_sync(0xffffffffu, d0, off);
        n0 += __shfl_xor_sync(0xffffffffu, n0, off);
        d1 += __shfl_xor_sync(0xffffffffu, d1, off);
        n1 += __shfl_xor_sync(0xffffffffu, n1, off);
    }
    if (lane == 0) {
        g_dist[b * TOKENS + r]     = d0 / fmaxf(sqrtf(n0), 1e-8f);
        g_dist[b * TOKENS + r + 1] = d1 / fmaxf(sqrtf(n1), 1e-8f);
    }
}

// ---------------------------------------------------------------------------
// Kernel 2: top-8 argmax rounds (stable ties -> lower index), bounding box.
// ---------------------------------------------------------------------------
__global__ void topk_kernel() {
    int b = blockIdx.x;
    int lane = threadIdx.x;                   // 32 threads
    __shared__ float dist[TOKENS];
    for (int i = lane; i < TOKENS; i += 32) dist[i] = g_dist[b * TOKENS + i];
    __syncwarp();

    int minx = FH, maxx = -1, miny = FH, maxy = -1;
#pragma unroll 1
    for (int k = 0; k < TOPK; ++k) {
        float best = -FLT_MAX; int bi = TOKENS;
        for (int i = lane; i < TOKENS; i += 32) {
            float v = dist[i];
            if (v > best) { best = v; bi = i; }   // strict > keeps lowest idx
        }
#pragma unroll
        for (int off = 16; off; off >>= 1) {
            float ov = __shfl_xor_sync(0xffffffffu, best, off);
            int   oi = __shfl_xor_sync(0xffffffffu, bi,   off);
            if (ov > best || (ov == best && oi < bi)) { best = ov; bi = oi; }
        }
        if (lane == 0) dist[bi] = -FLT_MAX;
        __syncwarp();
        int ix = bi / FH, iy = bi % FH;
        minx = min(minx, ix); maxx = max(maxx, ix);
        miny = min(miny, iy); maxy = max(maxy, iy);
    }
    if (lane == 0) {
        int x_i = minx * PATCH, x_f = maxx * PATCH;
        int y_i = miny * PATCH, y_f = maxy * PATCH;
        g_box[b][0] = max(x_i, 0);
        g_box[b][1] = min(max(x_f, x_i + PATCH), IMG);
        g_box[b][2] = max(y_i, 0);
        g_box[b][3] = min(max(y_f, y_i + PATCH), IMG);
    }
}

// ---------------------------------------------------------------------------
// Kernel 3: separable bilinear crop-resize, warp-autonomous, shuffle-tap
// phase A. A warp's 32 horizontal taps live in a 33-float window at a
// warp-uniform base (wstep <= 1): load src[base+lane] (one contiguous LDG,
// 4-5 sectors) + src[base+32] (broadcast, 1 sector), then both taps come
// from 2 SHFLs -> ~50% fewer L1 sectors than two spanned LDGs per row.
// Loads clamped to y1-1: clamped lanes are never consumed (all needed
// indices <= y1-1), and no OOB at the tensor edge.
// Phase B: vertical lerp, float4 LDS + __stcs STG.128.
// ---------------------------------------------------------------------------
#define ROWG 16
__global__ void __launch_bounds__(448) resize_kernel(
        const float* __restrict__ images, float* __restrict__ out) {
    int blk = blockIdx.x;
    int g  = blk % (IMG / ROWG);
    int t  = blk / (IMG / ROWG);
    int c  = t % 3;
    int b  = t / 3;
    int ty0 = g * ROWG;
    int tid  = threadIdx.x;
    int warp = tid >> 5;                      // 0..13
    int lane = tid & 31;
    int col  = (warp << 5) + lane;            // this thread's output column

    __shared__ __align__(16) float hrow[(ROWG + 1) * IMG];  // 29.8 KB

    int4 bx = *(const int4*)&g_box[b][0];
    int x0 = bx.x, x1 = bx.y, y0 = bx.z, y1 = bx.w;

    const float scale = 1.0f / (float)(IMG - 1);
    float hstep = ((float)(x1 - x0) - 1.0f) * scale;   // <= 1
    float wstep = ((float)(y1 - y0) - 1.0f) * scale;   // <= 1

    int rlo = (int)floorf((float)x0 + (float)ty0 * hstep);
    int rhi = min((int)floorf((float)x0 + (float)(ty0 + ROWG - 1) * hstep) + 1,
                  x1 - 1);
    int nrows = rhi - rlo + 1;                // <= 17

    const float* src = images + (size_t)(b * 3 + c) * IMG * IMG;

    // Phase A: horizontal lerp via warp-window load + shuffles
    {
        float sx  = (float)y0 + (float)col * wstep;
        int   xlo = (int)floorf(sx);
        int   xhi = min(xlo + 1, y1 - 1);
        float wx  = sx - (float)xlo;
        // warp-uniform window base = xlo of lane 0
        int   base = (int)floorf((float)y0 + (float)(warp << 5) * wstep);
        int   i0 = xlo - base;                // in [0, 31]
        int   i1 = xhi - base;                // in [0, 32]
        int   li  = min(base + lane, y1 - 1); // clamped: never consumed if clamped
        int   l32 = min(base + 32,  y1 - 1);

        const float* p = src + (size_t)rlo * IMG;
#pragma unroll
        for (int rr = 0; rr < ROWG + 1; ++rr) {
            if (rr < nrows) {
                const float* prow = p + (size_t)rr * IMG;
                float v = __ldg(prow + li);   // contiguous 32-float window
                float e = __ldg(prow + l32);  // broadcast (1 sector)
                float a  = __shfl_sync(0xffffffffu, v, i0);
                float tv = __shfl_sync(0xffffffffu, v, i1 & 31);
                float bv = (i1 < 32) ? tv : e;
                hrow[rr * IMG + col] = a + wx * (bv - a);
            }
        }
    }
    __syncwarp();

    // Phase B: vertical lerp over this warp's 32-column window
    float* obase = out + (size_t)(b * 3 + c) * IMG * IMG;
#pragma unroll
    for (int it = 0; it < ROWG / 4; ++it) {
        int j   = (it << 5) + lane;
        int tyl = j >> 3;
        int q   = j & 7;
        int txq = (warp << 3) + q;
        int ty  = ty0 + tyl;

        float sy  = (float)x0 + (float)ty * hstep;
        int   ylo = (int)floorf(sy);
        int   yhi = min(ylo + 1, x1 - 1);
        float wy  = sy - (float)ylo;

        float4 h0 = ((const float4*)(hrow + (ylo - rlo) * IMG))[txq];
        float4 h1 = ((const float4*)(hrow + (yhi - rlo) * IMG))[txq];
        float4 res;
        res.x = h0.x + wy * (h1.x - h0.x);
        res.y = h0.y + wy * (h1.y - h0.y);
        res.z = h0.z + wy * (h1.z - h0.z);
        res.w = h0.w + wy * (h1.w - h0.w);
        __stcs((float4*)(obase + (size_t)ty * IMG) + txq, res);
    }
}

// ---------------------------------------------------------------------------
extern "C" void kernel_launch(void* const* d_in, const int* in_sizes, int n_in,
                              void* d_out, int out_size) {
    const float* x      = (const float*)d_in[0];
    const float* images = (const float*)d_in[1];
    const int X_ELEMS   = NB * 785 * DIM;
    if (n_in >= 2 && in_sizes[0] != X_ELEMS) {
        x      = (const float*)d_in[1];
        images = (const float*)d_in[0];
    }
    float* out = (float*)d_out;

    dim3 g1(NB, 49);
    sim_kernel<<<g1, 256>>>(x);
    topk_kernel<<<NB, 32>>>();
    resize_kernel<<<NB * 3 * (IMG / ROWG), 448>>>(images, out);
}

// round 16
// speedup vs baseline: 1.2149x; 1.2149x over previous
#include <cuda_runtime.h>
#include <math.h>
#include <float.h>

#define NB      64
#define TOKENS  784
#define DIM     768
#define FH      28
#define IMG     448
#define TOPK    8
#define PATCH   16

__device__ float g_dist[NB * TOKENS];
__device__ int   g_box[NB][4];   // x0, x1, y0, y1

// ---------------------------------------------------------------------------
// Kernel 1: score = dot(g, l) / ||l||  (g-norm positive per-batch constant
// -> same ordering as cosine). grid (64,49) x 256, 2 rows per warp (the
// empirically best config: 3136 blocks, 12 in-flight LDG.128 per warp).
// ---------------------------------------------------------------------------
__global__ void __launch_bounds__(256) sim_kernel(const float* __restrict__ x) {
    int b = blockIdx.x;
    int s = blockIdx.y;                       // 0..48 -> 16 rows per block
    const float* xb = x + (size_t)b * 785 * DIM;

    __shared__ float4 g_sh[DIM / 4];          // CLS token, 3 KB
    int tid = threadIdx.x;
    if (tid < DIM / 4) g_sh[tid] = ((const float4*)xb)[tid];
    __syncthreads();

    int warp = tid >> 5, lane = tid & 31;
    int r = s * 16 + warp * 2;                // this warp's row pair
    const float4* l0 = (const float4*)(xb + (size_t)(1 + r) * DIM);
    const float4* l1 = (const float4*)(xb + (size_t)(2 + r) * DIM);
    float d0 = 0.f, n0 = 0.f, d1 = 0.f, n1 = 0.f;
#pragma unroll
    for (int j = 0; j < 6; ++j) {
        float4 a = l0[lane + 32 * j];
        float4 c = l1[lane + 32 * j];
        float4 g = g_sh[lane + 32 * j];
        d0 += a.x * g.x + a.y * g.y + a.z * g.z + a.w * g.w;
        n0 += a.x * a.x + a.y * a.y + a.z * a.z + a.w * a.w;
        d1 += c.x * g.x + c.y * g.y + c.z * g.z + c.w * g.w;
        n1 += c.x * c.x + c.y * c.y + c.z * c.z + c.w * c.w;
    }
#pragma unroll
    for (int off = 16; off; off >>= 1) {
        d0 += __shfl_xor_sync(0xffffffffu, d0, off);
        n0 += __shfl_xor_sync(0xffffffffu, n0, off);
        d1 += __shfl_xor_sync(0xffffffffu, d1, off);
        n1 += __shfl_xor_sync(0xffffffffu, n1, off);
    }
    if (lane == 0) {
        g_dist[b * TOKENS + r]     = d0 / fmaxf(sqrtf(n0), 1e-8f);
        g_dist[b * TOKENS + r + 1] = d1 / fmaxf(sqrtf(n1), 1e-8f);
    }
}

// ---------------------------------------------------------------------------
// Kernel 2: top-8 argmax rounds (stable ties -> lower index), bounding box.
// ---------------------------------------------------------------------------
__global__ void topk_kernel() {
    int b = blockIdx.x;
    int lane = threadIdx.x;                   // 32 threads
    __shared__ float dist[TOKENS];
    for (int i = lane; i < TOKENS; i += 32) dist[i] = g_dist[b * TOKENS + i];
    __syncwarp();

    int minx = FH, maxx = -1, miny = FH, maxy = -1;
#pragma unroll 1
    for (int k = 0; k < TOPK; ++k) {
        float best = -FLT_MAX; int bi = TOKENS;
        for (int i = lane; i < TOKENS; i += 32) {
            float v = dist[i];
            if (v > best) { best = v; bi = i; }   // strict > keeps lowest idx
        }
#pragma unroll
        for (int off = 16; off; off >>= 1) {
            float ov = __shfl_xor_sync(0xffffffffu, best, off);
            int   oi = __shfl_xor_sync(0xffffffffu, bi,   off);
            if (ov > best || (ov == best && oi < bi)) { best = ov; bi = oi; }
        }
        if (lane == 0) dist[bi] = -FLT_MAX;
        __syncwarp();
        int ix = bi / FH, iy = bi % FH;
        minx = min(minx, ix); maxx = max(maxx, ix);
        miny = min(miny, iy); maxy = max(maxy, iy);
    }
    if (lane == 0) {
        int x_i = minx * PATCH, x_f = maxx * PATCH;
        int y_i = miny * PATCH, y_f = maxy * PATCH;
        g_box[b][0] = max(x_i, 0);
        g_box[b][1] = min(max(x_f, x_i + PATCH), IMG);
        g_box[b][2] = max(y_i, 0);
        g_box[b][3] = min(max(y_f, y_i + PATCH), IMG);
    }
}

// ---------------------------------------------------------------------------
// Kernel 3: separable bilinear crop-resize, register-resident, zero smem.
// Block = (b, c, 16 output rows), 448 threads = one output column each.
// Phase A: all <=17 source rows h-lerped into a REGISTER array h[] — the
//   34 LDGs are mutually independent and issued in an unrolled burst
//   (MLP ~34/thread; this is the fix for R5's serialized rolling version).
// Phase B: k-unrolled loop over source intervals [rlo+k, rlo+k+1): the
//   inner advance over output rows is block-uniform (no divergence) and
//   h[k] / h[k+1] are statically indexed in each unrolled copy -> stays in
//   registers. Coalesced scalar __stcs stores (lane = column).
// Deletes ALL smem traffic (17 STS + 8 LDS.128 per thread) and the sync.
// ---------------------------------------------------------------------------
#define ROWG 16
__global__ void __launch_bounds__(448) resize_kernel(
        const float* __restrict__ images, float* __restrict__ out) {
    int blk = blockIdx.x;
    int g  = blk % (IMG / ROWG);
    int t  = blk / (IMG / ROWG);
    int c  = t % 3;
    int b  = t / 3;
    int ty0 = g * ROWG;
    int col = threadIdx.x;                    // output column, 0..447

    int4 bx = *(const int4*)&g_box[b][0];
    int x0 = bx.x, x1 = bx.y, y0 = bx.z, y1 = bx.w;

    const float scale = 1.0f / (float)(IMG - 1);
    float hstep = ((float)(x1 - x0) - 1.0f) * scale;   // <= 1
    float wstep = ((float)(y1 - y0) - 1.0f) * scale;   // <= 1
    float x0f = (float)x0;

    int rlo = (int)floorf(x0f + (float)ty0 * hstep);
    int rhi = min((int)floorf(x0f + (float)(ty0 + ROWG - 1) * hstep) + 1,
                  x1 - 1);
    int nrows = rhi - rlo + 1;                // <= 17

    // horizontal taps (fixed per thread)
    float sx  = (float)y0 + (float)col * wstep;
    int   xlo = (int)floorf(sx);
    int   xhi = min(xlo + 1, y1 - 1);
    float wx  = sx - (float)xlo;

    const float* src = images + (size_t)(b * 3 + c) * IMG * IMG;
    const float* p = src + (size_t)rlo * IMG;

    // Phase A: h-lerp all needed source rows into registers (34 indep LDGs)
    float h[ROWG + 1];
#pragma unroll
    for (int j = 0; j < ROWG + 1; ++j) {
        if (j < nrows) {
            float a  = __ldg(p + (size_t)j * IMG + xlo);
            float bv = __ldg(p + (size_t)j * IMG + xhi);
            h[j] = a + wx * (bv - a);
        }
    }

    // Phase B: walk source intervals; inner advance is block-uniform.
    float* op = out + ((size_t)(b * 3 + c) * IMG + ty0) * IMG + col;
    int ty = 0;
#pragma unroll
    for (int k = 0; k < ROWG + 1; ++k) {
        if (ty >= ROWG) break;
        // hn: next h value, clamped at the top edge (yhi = min(ylo+1, x1-1))
        float hc = h[k];
        float hn = (rlo + k + 1 <= rhi) ? h[(k + 1 <= ROWG) ? (k + 1) : k] : hc;
        while (ty < ROWG) {
            float sy  = x0f + (float)(ty0 + ty) * hstep;
            int   ylo = (int)floorf(sy);
            if (ylo != rlo + k) break;        // block-uniform condition
            float wy  = sy - (float)ylo;
            __stcs(op + (size_t)ty * IMG, hc + wy * (hn - hc));
            ++ty;
        }
    }
}

// ---------------------------------------------------------------------------
extern "C" void kernel_launch(void* const* d_in, const int* in_sizes, int n_in,
                              void* d_out, int out_size) {
    const float* x      = (const float*)d_in[0];
    const float* images = (const float*)d_in[1];
    const int X_ELEMS   = NB * 785 * DIM;
    if (n_in >= 2 && in_sizes[0] != X_ELEMS) {
        x      = (const float*)d_in[1];
        images = (const float*)d_in[0];
    }
    float* out = (float*)d_out;

    dim3 g1(NB, 49);
    sim_kernel<<<g1, 256>>>(x);
    topk_kernel<<<NB, 32>>>();
    resize_kernel<<<NB * 3 * (IMG / ROWG), 448>>>(images, out);
}